// round 2
// baseline (speedup 1.0000x reference)
#include <cuda_runtime.h>
#include <math.h>

// ---------------- scratch (static __device__, no allocation) ----------------
__device__ float g_bufA[65536u * 256u];   // 64 MB ping
__device__ float g_bufB[65536u * 256u];   // 64 MB pong
__device__ float g_Wc  [4 * 256 * 256];   // packed W1..W4
__device__ float g_s0  [4 * 256 * 256];
__device__ float g_s1  [4 * 256 * 256];
__device__ float g_s2  [4 * 256 * 256];
__device__ float g_s3  [4 * 256 * 256];
__device__ float g_winv[4 * 256 * 256];   // W^-1 per layer

// ---------------- pack w1..w4 into contiguous buffer ----------------
__global__ void pack4_kernel(const float* __restrict__ w1, const float* __restrict__ w2,
                             const float* __restrict__ w3, const float* __restrict__ w4,
                             float* __restrict__ dst) {
    int idx = blockIdx.x * blockDim.x + threadIdx.x;          // 0..65535
    const float* src = (blockIdx.y == 0) ? w1 : (blockIdx.y == 1) ? w2
                     : (blockIdx.y == 2) ? w3 : w4;
    dst[blockIdx.y * 65536 + idx] = src[idx];
}

// ---------------- small 256x256x256 GEMM: C = (sa*A + aI)(sb*B + bI) --------
// batched over 4 matrices via blockIdx.z; tile 64x64, 4x4/thread, BK=16
__global__ __launch_bounds__(256) void gemm_small_kernel(
    const float* __restrict__ A, const float* __restrict__ B, float* __restrict__ C,
    float sa, float adiag, float sb, float bdiag)
{
    int mat = blockIdx.z;
    A += mat * 65536; B += mat * 65536; C += mat * 65536;
    __shared__ float As[16][64];
    __shared__ float Bs[16][68];
    int tid = threadIdx.x;
    int tx = tid & 15, ty = tid >> 4;
    int row0 = blockIdx.x * 64;
    int col0 = blockIdx.y * 64;
    float acc[4][4] = {};
    for (int k0 = 0; k0 < 256; k0 += 16) {
        {   // A tile 64x16, transposed store
            int r = tid >> 2;
            int c = (tid & 3) * 4;
            float4 v = *reinterpret_cast<const float4*>(&A[(size_t)(row0 + r) * 256 + k0 + c]);
            int gr = row0 + r, gc = k0 + c;
            As[c + 0][r] = sa * v.x + ((gr == gc + 0) ? adiag : 0.f);
            As[c + 1][r] = sa * v.y + ((gr == gc + 1) ? adiag : 0.f);
            As[c + 2][r] = sa * v.z + ((gr == gc + 2) ? adiag : 0.f);
            As[c + 3][r] = sa * v.w + ((gr == gc + 3) ? adiag : 0.f);
        }
        {   // B tile 16x64
            int r = tid >> 4;
            int c = (tid & 15) * 4;
            float4 v = *reinterpret_cast<const float4*>(&B[(size_t)(k0 + r) * 256 + col0 + c]);
            int gk = k0 + r, gc = col0 + c;
            Bs[r][c + 0] = sb * v.x + ((gk == gc + 0) ? bdiag : 0.f);
            Bs[r][c + 1] = sb * v.y + ((gk == gc + 1) ? bdiag : 0.f);
            Bs[r][c + 2] = sb * v.z + ((gk == gc + 2) ? bdiag : 0.f);
            Bs[r][c + 3] = sb * v.w + ((gk == gc + 3) ? bdiag : 0.f);
        }
        __syncthreads();
        #pragma unroll
        for (int kk = 0; kk < 16; kk++) {
            float a[4], b[4];
            #pragma unroll
            for (int i = 0; i < 4; i++) a[i] = As[kk][ty * 4 + i];
            #pragma unroll
            for (int j = 0; j < 4; j++) b[j] = Bs[kk][tx * 4 + j];
            #pragma unroll
            for (int i = 0; i < 4; i++)
                #pragma unroll
                for (int j = 0; j < 4; j++)
                    acc[i][j] += a[i] * b[j];
        }
        __syncthreads();
    }
    #pragma unroll
    for (int i = 0; i < 4; i++)
        #pragma unroll
        for (int j = 0; j < 4; j++)
            C[(size_t)(row0 + ty * 4 + i) * 256 + col0 + tx * 4 + j] = acc[i][j];
}

// ---------------- big GEMM: C[M,256] = A[M,256] @ B[256,256], fused epilogue
// mode 0: out = acc (+bias1);  mode 1: v = acc (+bias1); out = v + tanh(v) + bias2
#define BM 128
#define BN 128
#define BK 16
__global__ __launch_bounds__(256) void gemm_big_kernel(
    const float* __restrict__ A, const float* __restrict__ B, float* __restrict__ C,
    const float* __restrict__ bias1, const float* __restrict__ bias2, int mode)
{
    __shared__ float As[BK][BM];
    __shared__ float Bs[BK][BN];
    int bm = blockIdx.x * BM;
    int bn = blockIdx.y * BN;
    int tid = threadIdx.x;
    int tx = tid & 15, ty = tid >> 4;
    float acc[8][8] = {};

    for (int k0 = 0; k0 < 256; k0 += BK) {
        #pragma unroll
        for (int i = 0; i < 2; i++) {       // A tile: 128x16 = 512 float4
            int f = tid + i * 256;
            int r = f >> 2;
            int c = (f & 3) * 4;
            float4 v = *reinterpret_cast<const float4*>(&A[(size_t)(bm + r) * 256 + k0 + c]);
            As[c + 0][r] = v.x; As[c + 1][r] = v.y;
            As[c + 2][r] = v.z; As[c + 3][r] = v.w;
        }
        #pragma unroll
        for (int i = 0; i < 2; i++) {       // B tile: 16x128 = 512 float4
            int f = tid + i * 256;
            int r = f >> 5;
            int c = (f & 31) * 4;
            *reinterpret_cast<float4*>(&Bs[r][c]) =
                *reinterpret_cast<const float4*>(&B[(size_t)(k0 + r) * 256 + bn + c]);
        }
        __syncthreads();
        #pragma unroll
        for (int kk = 0; kk < BK; kk++) {
            float4 a0 = *reinterpret_cast<const float4*>(&As[kk][ty * 8]);
            float4 a1 = *reinterpret_cast<const float4*>(&As[kk][ty * 8 + 4]);
            float4 b0 = *reinterpret_cast<const float4*>(&Bs[kk][tx * 8]);
            float4 b1 = *reinterpret_cast<const float4*>(&Bs[kk][tx * 8 + 4]);
            float a[8] = {a0.x, a0.y, a0.z, a0.w, a1.x, a1.y, a1.z, a1.w};
            float b[8] = {b0.x, b0.y, b0.z, b0.w, b1.x, b1.y, b1.z, b1.w};
            #pragma unroll
            for (int i = 0; i < 8; i++)
                #pragma unroll
                for (int j = 0; j < 8; j++)
                    acc[i][j] += a[i] * b[j];
        }
        __syncthreads();
    }

    float bb1[8], bb2[8];
    #pragma unroll
    for (int j = 0; j < 8; j++) {
        int col = bn + tx * 8 + j;
        bb1[j] = bias1 ? bias1[col] : 0.f;
        bb2[j] = (mode == 1) ? bias2[col] : 0.f;
    }
    #pragma unroll
    for (int i = 0; i < 8; i++) {
        int row = bm + ty * 8 + i;
        #pragma unroll
        for (int j = 0; j < 8; j++) {
            int col = bn + tx * 8 + j;
            float v = acc[i][j] + bb1[j];
            if (mode == 1) v = v + tanhf(v) + bb2[j];
            C[(size_t)row * 256 + col] = v;
        }
    }
}

// ---------------- logits + softmax: one warp per row ----------------
__global__ __launch_bounds__(256) void final_softmax_kernel(
    const float* __restrict__ Z, const float* __restrict__ w_out,
    const float* __restrict__ b_out, float* __restrict__ out)
{
    __shared__ float ws[2560];
    __shared__ float bs[10];
    int tid = threadIdx.x;
    for (int i = tid; i < 2560; i += 256) ws[i] = w_out[i];
    if (tid < 10) bs[tid] = b_out[tid];
    __syncthreads();

    int warp = tid >> 5, lane = tid & 31;
    int row = blockIdx.x * 8 + warp;
    float acc[10] = {};
    const float4* zr = reinterpret_cast<const float4*>(Z + (size_t)row * 256);
    for (int i = lane; i < 64; i += 32) {
        float4 v = zr[i];
        int k = i * 4;
        #pragma unroll
        for (int j = 0; j < 10; j++)
            acc[j] += v.x * ws[(k + 0) * 10 + j] + v.y * ws[(k + 1) * 10 + j]
                    + v.z * ws[(k + 2) * 10 + j] + v.w * ws[(k + 3) * 10 + j];
    }
    #pragma unroll
    for (int j = 0; j < 10; j++) {
        float v = acc[j];
        #pragma unroll
        for (int o = 16; o; o >>= 1) v += __shfl_xor_sync(0xFFFFFFFFu, v, o);
        acc[j] = v;
    }
    if (lane == 0) {
        float m = -1e30f;
        #pragma unroll
        for (int j = 0; j < 10; j++) { acc[j] += bs[j]; m = fmaxf(m, acc[j]); }
        float s = 0.f;
        #pragma unroll
        for (int j = 0; j < 10; j++) { acc[j] = expf(acc[j] - m); s += acc[j]; }
        float inv = 1.0f / s;
        #pragma unroll
        for (int j = 0; j < 10; j++) out[(size_t)row * 10 + j] = acc[j] * inv;
    }
}

// ---------------- launch ----------------
extern "C" void kernel_launch(void* const* d_in, const int* in_sizes, int n_in,
                              void* d_out, int out_size) {
    // Resolve inputs by SIZE signature, robust to metadata ordering.
    // x: 65536*256 = 16777216; W matrices (w_in, w1..w4): 65536 each, in order;
    // biases (b_in, b1..b4): 256 each, in order; w_out: 2560; b_out: 10.
    const float* x = nullptr;
    const float* Wm[5] = {};  int nW = 0;   // w_in, w1..w4 (relative order preserved)
    const float* Bv[5] = {};  int nB = 0;   // b_in, b1..b4
    const float* w_out = nullptr;
    const float* b_out = nullptr;
    for (int i = 0; i < n_in; i++) {
        const float* p = (const float*)d_in[i];
        int sz = in_sizes[i];
        if (sz == 65536 * 256)      x = p;
        else if (sz == 65536)       { if (nW < 5) Wm[nW++] = p; }
        else if (sz == 256)         { if (nB < 5) Bv[nB++] = p; }
        else if (sz == 2560)        w_out = p;
        else if (sz == 10)          b_out = p;
    }
    const float* w_in = Wm[0];
    const float* w1 = Wm[1], *w2 = Wm[2], *w3 = Wm[3], *w4 = Wm[4];
    const float* b_in = Bv[0];
    const float* b1 = Bv[1], *b2 = Bv[2], *b3 = Bv[3], *b4 = Bv[4];
    int M = 65536;

    float *bufA, *bufB, *wc, *s0, *s1, *s2, *s3, *winv;
    cudaGetSymbolAddress((void**)&bufA, g_bufA);
    cudaGetSymbolAddress((void**)&bufB, g_bufB);
    cudaGetSymbolAddress((void**)&wc,   g_Wc);
    cudaGetSymbolAddress((void**)&s0,   g_s0);
    cudaGetSymbolAddress((void**)&s1,   g_s1);
    cudaGetSymbolAddress((void**)&s2,   g_s2);
    cudaGetSymbolAddress((void**)&s3,   g_s3);
    cudaGetSymbolAddress((void**)&winv, g_winv);

    // ---- invert W1..W4 via factored Neumann: W^-1 = (I-E)(I+E^2)(I+E^4)(I+E^8)
    pack4_kernel<<<dim3(256, 4), 256>>>(w1, w2, w3, w4, wc);
    dim3 sg(4, 4, 4);
    gemm_small_kernel<<<sg, 256>>>(wc, wc, s0,  1.f, -1.f, 1.f, -1.f); // E^2 = (W-I)(W-I)
    gemm_small_kernel<<<sg, 256>>>(s0, s0, s1,  1.f,  0.f, 1.f,  0.f); // E^4
    gemm_small_kernel<<<sg, 256>>>(s1, s1, s2,  1.f,  0.f, 1.f,  0.f); // E^8
    gemm_small_kernel<<<sg, 256>>>(wc, s0, s3, -1.f,  2.f, 1.f,  1.f); // (I-E)(I+E^2)
    gemm_small_kernel<<<sg, 256>>>(s3, s1, s0,  1.f,  0.f, 1.f,  1.f); // *(I+E^4)
    gemm_small_kernel<<<sg, 256>>>(s0, s2, winv,1.f,  0.f, 1.f,  1.f); // *(I+E^8) -> W^-1

    // ---- forward chain: 5 big GEMMs, elementwise fused into epilogues
    dim3 bg(M / BM, 256 / BN);
    // c1 = h0 + tanh(h0) + b1, h0 = x@w_in + b_in
    gemm_big_kernel<<<bg, 256>>>(x,    w_in,          bufA, b_in,    b1,      1);
    // z1 = c1@Winv1; c2 = z1 + tanh(z1) + b2
    gemm_big_kernel<<<bg, 256>>>(bufA, winv + 0,      bufB, nullptr, b2,      1);
    gemm_big_kernel<<<bg, 256>>>(bufB, winv + 65536,  bufA, nullptr, b3,      1);
    gemm_big_kernel<<<bg, 256>>>(bufA, winv + 131072, bufB, nullptr, b4,      1);
    // z4 = c4@Winv4 (plain)
    gemm_big_kernel<<<bg, 256>>>(bufB, winv + 196608, bufA, nullptr, nullptr, 0);

    // ---- logits + softmax
    final_softmax_kernel<<<M / 8, 256>>>(bufA, w_out, b_out, (float*)d_out);
}

// round 6
// speedup vs baseline: 1.8378x; 1.8378x over previous
#include <cuda_runtime.h>
#include <cuda_bf16.h>
#include <math.h>
#include <stdint.h>

// ======================= scratch (no allocation) ============================
__device__ float g_bufA[65536u * 256u];
__device__ float g_bufB[65536u * 256u];
__device__ float g_Wc  [4 * 65536];
__device__ float g_e2  [4 * 65536];
__device__ float g_e4  [4 * 65536];
__device__ float g_e8  [4 * 65536];
__device__ float g_p1  [4 * 65536];
__device__ float g_p2  [4 * 65536];
__device__ float g_winv[4 * 65536];
__device__ float g_wt  [5 * 65536];   // transposed: w_in^T, Winv1..4^T

// ======================= helpers ===========================================
__device__ __forceinline__ uint32_t smem_u32(const void* p) {
    uint32_t a;
    asm("{ .reg .u64 t; cvta.to.shared.u64 t, %1; cvt.u32.u64 %0, t; }"
        : "=r"(a) : "l"(p));
    return a;
}

#define STS128V(addr, r0, r1, r2, r3) \
    asm volatile("st.shared.v4.b32 [%0], {%1, %2, %3, %4};" \
        :: "r"(addr), "r"(r0), "r"(r1), "r"(r2), "r"(r3) : "memory")

__device__ __forceinline__ void ldsm_x4(uint32_t& r0, uint32_t& r1,
                                        uint32_t& r2, uint32_t& r3, uint32_t addr) {
    asm volatile("ldmatrix.sync.aligned.m8n8.x4.shared.b16 {%0,%1,%2,%3}, [%4];"
        : "=r"(r0), "=r"(r1), "=r"(r2), "=r"(r3) : "r"(addr));
}

__device__ __forceinline__ void mma16816(float* c, uint32_t a0, uint32_t a1,
                                         uint32_t a2, uint32_t a3,
                                         uint32_t b0, uint32_t b1) {
    asm volatile("mma.sync.aligned.m16n8k16.row.col.f32.bf16.bf16.f32 "
        "{%0,%1,%2,%3}, {%4,%5,%6,%7}, {%8,%9}, {%0,%1,%2,%3};"
        : "+f"(c[0]), "+f"(c[1]), "+f"(c[2]), "+f"(c[3])
        : "r"(a0), "r"(a1), "r"(a2), "r"(a3), "r"(b0), "r"(b1));
}

// 8 fp32 -> 4 packed bf16x2 hi words + 4 lo words (split precision)
__device__ __forceinline__ void split8(const float* f, uint32_t* hw, uint32_t* lw) {
    #pragma unroll
    for (int j = 0; j < 4; j++) {
        __nv_bfloat16 h0 = __float2bfloat16(f[2 * j]);
        __nv_bfloat16 h1 = __float2bfloat16(f[2 * j + 1]);
        float l0 = f[2 * j] - __bfloat162float(h0);
        float l1 = f[2 * j + 1] - __bfloat162float(h1);
        __nv_bfloat162 hp; hp.x = h0; hp.y = h1;
        __nv_bfloat162 lp; lp.x = __float2bfloat16(l0); lp.y = __float2bfloat16(l1);
        hw[j] = *(uint32_t*)&hp; lw[j] = *(uint32_t*)&lp;
    }
}

// ======================= weight prep kernels ================================
__global__ void pack4_kernel(const float* __restrict__ w1, const float* __restrict__ w2,
                             const float* __restrict__ w3, const float* __restrict__ w4,
                             float* __restrict__ dst) {
    int idx = blockIdx.x * blockDim.x + threadIdx.x;
    const float* src = (blockIdx.y == 0) ? w1 : (blockIdx.y == 1) ? w2
                     : (blockIdx.y == 2) ? w3 : w4;
    dst[blockIdx.y * 65536 + idx] = src[idx];
}

// batched small 256x256 GEMM stages for Neumann inversion
// stage 0: E2 = (W-I)(W-I);  stage 1: z<4 E4=E2*E2, z>=4 P1=(2I-W)(I+E2)
// stage 2: z<4 E8=E4*E4, z>=4 P2=P1*(I+E4);  stage 3: Winv=P2*(I+E8)
__global__ __launch_bounds__(256) void small_stage_kernel(
    int stage, const float* __restrict__ wc, float* __restrict__ e2,
    float* __restrict__ e4, float* __restrict__ e8,
    float* __restrict__ p1, float* __restrict__ p2, float* __restrict__ winv)
{
    int z = blockIdx.z;
    const float *Ap, *Bp; float* Cp;
    float sa = 1.f, ad = 0.f, sb = 1.f, bd = 0.f;
    if (stage == 0) { Ap = wc + z * 65536; Bp = Ap; Cp = e2 + z * 65536; ad = -1.f; bd = -1.f; }
    else if (stage == 1) {
        if (z < 4) { Ap = e2 + z * 65536; Bp = Ap; Cp = e4 + z * 65536; }
        else { int m = z - 4; Ap = wc + m * 65536; sa = -1.f; ad = 2.f;
               Bp = e2 + m * 65536; bd = 1.f; Cp = p1 + m * 65536; }
    } else if (stage == 2) {
        if (z < 4) { Ap = e4 + z * 65536; Bp = Ap; Cp = e8 + z * 65536; }
        else { int m = z - 4; Ap = p1 + m * 65536; Bp = e4 + m * 65536;
               bd = 1.f; Cp = p2 + m * 65536; }
    } else { Ap = p2 + z * 65536; Bp = e8 + z * 65536; bd = 1.f; Cp = winv + z * 65536; }

    __shared__ float As[32][33], Bs[32][33];
    int tid = threadIdx.x, tx = tid & 15, ty = tid >> 4;
    int r0 = blockIdx.x * 32, c0 = blockIdx.y * 32;
    float acc00 = 0.f, acc01 = 0.f, acc10 = 0.f, acc11 = 0.f;
    for (int k0 = 0; k0 < 256; k0 += 32) {
        #pragma unroll
        for (int it = 0; it < 4; it++) {
            int idx = tid + it * 256;
            int r = idx >> 5, cc = idx & 31;
            As[r][cc] = Ap[(r0 + r) * 256 + k0 + cc] * sa + ((r0 + r) == (k0 + cc) ? ad : 0.f);
            Bs[r][cc] = Bp[(k0 + r) * 256 + c0 + cc] * sb + ((k0 + r) == (c0 + cc) ? bd : 0.f);
        }
        __syncthreads();
        #pragma unroll
        for (int kk = 0; kk < 32; kk++) {
            float a0 = As[ty * 2][kk], a1 = As[ty * 2 + 1][kk];
            float b0 = Bs[kk][tx * 2], b1 = Bs[kk][tx * 2 + 1];
            acc00 += a0 * b0; acc01 += a0 * b1;
            acc10 += a1 * b0; acc11 += a1 * b1;
        }
        __syncthreads();
    }
    Cp[(r0 + ty * 2) * 256 + c0 + tx * 2]           = acc00;
    Cp[(r0 + ty * 2) * 256 + c0 + tx * 2 + 1]       = acc01;
    Cp[(r0 + ty * 2 + 1) * 256 + c0 + tx * 2]       = acc10;
    Cp[(r0 + ty * 2 + 1) * 256 + c0 + tx * 2 + 1]   = acc11;
}

// transpose w_in + Winv1..4 into g_wt (wt[z][n][k] = W[k][n])
__global__ void transpose5_kernel(const float* __restrict__ w_in,
                                  const float* __restrict__ winv,
                                  float* __restrict__ wt) {
    __shared__ float t[32][33];
    int z = blockIdx.z;
    const float* src = (z == 0) ? w_in : winv + (z - 1) * 65536;
    int x = blockIdx.x * 32 + threadIdx.x;
    int y = blockIdx.y * 32 + threadIdx.y;
    t[threadIdx.y][threadIdx.x] = src[y * 256 + x];
    __syncthreads();
    int ox = blockIdx.y * 32 + threadIdx.x;
    int oy = blockIdx.x * 32 + threadIdx.y;
    wt[z * 65536 + oy * 256 + ox] = t[threadIdx.x][threadIdx.y];
}

// ======================= big GEMM via mma.sync (HMMA) =======================
// C[M,256] = A[M,256] @ W, WT[n][k] = W[k][n] fp32 in global.
// Split-bf16: D = Ah*Bh + Ah*Bl + Al*Bh, fp32 accumulate in registers.
// CTA tile 128x128, 8 warps (4 M x 2 N), warp tile 32x64.
// K chunks of 32; smem tiles padded to 40 bf16/row (80B stride, LDSM conflict-free).
// Epilogue: v = D (+bias1); mode1: v = v + tanh(v) + bias2.
#define PADK 40
__global__ __launch_bounds__(256) void gemm_mma_kernel(
    const float* __restrict__ A, const float* __restrict__ WT, float* __restrict__ C,
    const float* __restrict__ bias1, const float* __restrict__ bias2, int mode)
{
    __shared__ __align__(16) __nv_bfloat16 sAh[128 * PADK];
    __shared__ __align__(16) __nv_bfloat16 sAl[128 * PADK];
    __shared__ __align__(16) __nv_bfloat16 sBh[128 * PADK];
    __shared__ __align__(16) __nv_bfloat16 sBl[128 * PADK];

    int tid = threadIdx.x, wid = tid >> 5, lane = tid & 31;
    int m0 = blockIdx.x * 128, bn = blockIdx.y * 128;
    int wm = wid & 3, wn = wid >> 2;          // warp covers rows wm*32.., cols wn*64..

    uint32_t bAh = smem_u32(sAh), bAl = smem_u32(sAl);
    uint32_t bBh = smem_u32(sBh), bBl = smem_u32(sBl);

    float acc[2][4][2][4];                    // [mfrag][nfp][sub][4]
    #pragma unroll
    for (int i = 0; i < 2; i++)
        #pragma unroll
        for (int j = 0; j < 4; j++)
            #pragma unroll
            for (int s = 0; s < 2; s++)
                #pragma unroll
                for (int q = 0; q < 4; q++) acc[i][j][s][q] = 0.f;

    for (int c = 0; c < 8; c++) {
        int kc = c * 32;
        // ---- fill A chunk: 128 rows x 32 k -> hi/lo bf16
        #pragma unroll
        for (int it = 0; it < 2; it++) {
            int g = tid + it * 256;           // 0..511
            int m = g >> 2;                   // 0..127
            int kg = (g & 3) * 8;             // 0,8,16,24
            const float* src = A + (size_t)(m0 + m) * 256 + kc + kg;
            float4 v0 = *(const float4*)src;
            float4 v1 = *(const float4*)(src + 4);
            float f[8] = {v0.x, v0.y, v0.z, v0.w, v1.x, v1.y, v1.z, v1.w};
            uint32_t hw[4], lw[4];
            split8(f, hw, lw);
            uint32_t off = (uint32_t)(m * PADK + kg) * 2;
            STS128V(bAh + off, hw[0], hw[1], hw[2], hw[3]);
            STS128V(bAl + off, lw[0], lw[1], lw[2], lw[3]);
        }
        // ---- fill B chunk: 128 n-rows x 32 k from WT
        #pragma unroll
        for (int it = 0; it < 2; it++) {
            int g = tid + it * 256;
            int n = g >> 2;
            int kg = (g & 3) * 8;
            const float* src = WT + (size_t)(bn + n) * 256 + kc + kg;
            float4 v0 = *(const float4*)src;
            float4 v1 = *(const float4*)(src + 4);
            float f[8] = {v0.x, v0.y, v0.z, v0.w, v1.x, v1.y, v1.z, v1.w};
            uint32_t hw[4], lw[4];
            split8(f, hw, lw);
            uint32_t off = (uint32_t)(n * PADK + kg) * 2;
            STS128V(bBh + off, hw[0], hw[1], hw[2], hw[3]);
            STS128V(bBl + off, lw[0], lw[1], lw[2], lw[3]);
        }
        __syncthreads();

        // ---- compute: 2 k-steps of 16
        #pragma unroll
        for (int ks = 0; ks < 2; ks++) {
            int koff = ks * 16 + ((lane >> 4) << 3);    // per-lane k offset
            // A fragments: mf 0/1, hi & lo
            uint32_t ah[2][4], al[2][4];
            #pragma unroll
            for (int mf = 0; mf < 2; mf++) {
                uint32_t row = (uint32_t)(wm * 32 + mf * 16 + (lane & 15));
                uint32_t o = (row * PADK + koff) * 2;
                ldsm_x4(ah[mf][0], ah[mf][1], ah[mf][2], ah[mf][3], bAh + o);
                ldsm_x4(al[mf][0], al[mf][1], al[mf][2], al[mf][3], bAl + o);
            }
            #pragma unroll
            for (int nfp = 0; nfp < 4; nfp++) {
                uint32_t row = (uint32_t)(wn * 64 + nfp * 16 + (lane & 15));
                uint32_t o = (row * PADK + koff) * 2;
                uint32_t bh0, bh1, bh2, bh3, bl0, bl1, bl2, bl3;
                ldsm_x4(bh0, bh1, bh2, bh3, bBh + o);
                ldsm_x4(bl0, bl1, bl2, bl3, bBl + o);
                // sub0 = rows nfp*16..+7 -> {r0,r2}; sub1 = +8..15 -> {r1,r3}
                #pragma unroll
                for (int mf = 0; mf < 2; mf++) {
                    mma16816(acc[mf][nfp][0], ah[mf][0], ah[mf][1], ah[mf][2], ah[mf][3], bh0, bh2);
                    mma16816(acc[mf][nfp][0], ah[mf][0], ah[mf][1], ah[mf][2], ah[mf][3], bl0, bl2);
                    mma16816(acc[mf][nfp][0], al[mf][0], al[mf][1], al[mf][2], al[mf][3], bh0, bh2);
                    mma16816(acc[mf][nfp][1], ah[mf][0], ah[mf][1], ah[mf][2], ah[mf][3], bh1, bh3);
                    mma16816(acc[mf][nfp][1], ah[mf][0], ah[mf][1], ah[mf][2], ah[mf][3], bl1, bl3);
                    mma16816(acc[mf][nfp][1], al[mf][0], al[mf][1], al[mf][2], al[mf][3], bh1, bh3);
                }
            }
        }
        __syncthreads();
    }

    // ---- epilogue
    #pragma unroll
    for (int mf = 0; mf < 2; mf++) {
        int row = m0 + wm * 32 + mf * 16 + (lane >> 2);
        #pragma unroll
        for (int nfp = 0; nfp < 4; nfp++) {
            #pragma unroll
            for (int s = 0; s < 2; s++) {
                int col = bn + wn * 64 + nfp * 16 + s * 8 + (lane & 3) * 2;
                float b1a = bias1 ? __ldg(bias1 + col)     : 0.f;
                float b1b = bias1 ? __ldg(bias1 + col + 1) : 0.f;
                float b2a = mode  ? __ldg(bias2 + col)     : 0.f;
                float b2b = mode  ? __ldg(bias2 + col + 1) : 0.f;
                float v0 = acc[mf][nfp][s][0] + b1a;
                float v1 = acc[mf][nfp][s][1] + b1b;
                float v2 = acc[mf][nfp][s][2] + b1a;
                float v3 = acc[mf][nfp][s][3] + b1b;
                if (mode) {
                    v0 = v0 + tanhf(v0) + b2a;
                    v1 = v1 + tanhf(v1) + b2b;
                    v2 = v2 + tanhf(v2) + b2a;
                    v3 = v3 + tanhf(v3) + b2b;
                }
                *(float2*)(C + (size_t)row * 256 + col)       = make_float2(v0, v1);
                *(float2*)(C + (size_t)(row + 8) * 256 + col) = make_float2(v2, v3);
            }
        }
    }
}

// ======================= logits + softmax ===================================
__global__ __launch_bounds__(256) void final_softmax_kernel(
    const float* __restrict__ Z, const float* __restrict__ w_out,
    const float* __restrict__ b_out, float* __restrict__ out)
{
    __shared__ float ws[2560];
    __shared__ float bs[10];
    int tid = threadIdx.x;
    for (int i = tid; i < 2560; i += 256) ws[i] = w_out[i];
    if (tid < 10) bs[tid] = b_out[tid];
    __syncthreads();

    int warp = tid >> 5, lane = tid & 31;
    int row = blockIdx.x * 8 + warp;
    float acc[10] = {};
    const float4* zr = reinterpret_cast<const float4*>(Z + (size_t)row * 256);
    for (int i = lane; i < 64; i += 32) {
        float4 v = zr[i];
        int k = i * 4;
        #pragma unroll
        for (int j = 0; j < 10; j++)
            acc[j] += v.x * ws[(k + 0) * 10 + j] + v.y * ws[(k + 1) * 10 + j]
                    + v.z * ws[(k + 2) * 10 + j] + v.w * ws[(k + 3) * 10 + j];
    }
    #pragma unroll
    for (int j = 0; j < 10; j++) {
        float v = acc[j];
        #pragma unroll
        for (int o = 16; o; o >>= 1) v += __shfl_xor_sync(0xFFFFFFFFu, v, o);
        acc[j] = v;
    }
    if (lane == 0) {
        float m = -1e30f;
        #pragma unroll
        for (int j = 0; j < 10; j++) { acc[j] += bs[j]; m = fmaxf(m, acc[j]); }
        float s = 0.f;
        #pragma unroll
        for (int j = 0; j < 10; j++) { acc[j] = expf(acc[j] - m); s += acc[j]; }
        float inv = 1.0f / s;
        #pragma unroll
        for (int j = 0; j < 10; j++) out[(size_t)row * 10 + j] = acc[j] * inv;
    }
}

// ======================= launch =============================================
extern "C" void kernel_launch(void* const* d_in, const int* in_sizes, int n_in,
                              void* d_out, int out_size) {
    const float* x = nullptr;
    const float* Wm[5] = {};  int nW = 0;
    const float* Bv[5] = {};  int nB = 0;
    const float* w_out = nullptr;
    const float* b_out = nullptr;
    for (int i = 0; i < n_in; i++) {
        const float* p = (const float*)d_in[i];
        int sz = in_sizes[i];
        if (sz == 65536 * 256)      x = p;
        else if (sz == 65536)       { if (nW < 5) Wm[nW++] = p; }
        else if (sz == 256)         { if (nB < 5) Bv[nB++] = p; }
        else if (sz == 2560)        w_out = p;
        else if (sz == 10)          b_out = p;
    }
    const float* w_in = Wm[0];
    const float* b_in = Bv[0];
    int M = 65536;

    float *bufA, *bufB, *wc, *e2, *e4, *e8, *p1, *p2, *winv, *wt;
    cudaGetSymbolAddress((void**)&bufA, g_bufA);
    cudaGetSymbolAddress((void**)&bufB, g_bufB);
    cudaGetSymbolAddress((void**)&wc,   g_Wc);
    cudaGetSymbolAddress((void**)&e2,   g_e2);
    cudaGetSymbolAddress((void**)&e4,   g_e4);
    cudaGetSymbolAddress((void**)&e8,   g_e8);
    cudaGetSymbolAddress((void**)&p1,   g_p1);
    cudaGetSymbolAddress((void**)&p2,   g_p2);
    cudaGetSymbolAddress((void**)&winv, g_winv);
    cudaGetSymbolAddress((void**)&wt,   g_wt);

    // ---- Neumann inverse of W1..W4: Winv = (I-E)(I+E^2)(I+E^4)(I+E^8), E=W-I
    pack4_kernel<<<dim3(256, 4), 256>>>(Wm[1], Wm[2], Wm[3], Wm[4], wc);
    small_stage_kernel<<<dim3(8, 8, 4), 256>>>(0, wc, e2, e4, e8, p1, p2, winv);
    small_stage_kernel<<<dim3(8, 8, 8), 256>>>(1, wc, e2, e4, e8, p1, p2, winv);
    small_stage_kernel<<<dim3(8, 8, 8), 256>>>(2, wc, e2, e4, e8, p1, p2, winv);
    small_stage_kernel<<<dim3(8, 8, 4), 256>>>(3, wc, e2, e4, e8, p1, p2, winv);

    // ---- transpose all 5 forward weights into wt
    transpose5_kernel<<<dim3(8, 8, 5), dim3(32, 32)>>>(w_in, winv, wt);

    // ---- forward chain: 5 HMMA GEMMs (grid covers M x 2 column blocks)
    dim3 bg(M / 128, 2);
    gemm_mma_kernel<<<bg, 256>>>(x,    wt + 0 * 65536, bufA, b_in,    Bv[1], 1);
    gemm_mma_kernel<<<bg, 256>>>(bufA, wt + 1 * 65536, bufB, nullptr, Bv[2], 1);
    gemm_mma_kernel<<<bg, 256>>>(bufB, wt + 2 * 65536, bufA, nullptr, Bv[3], 1);
    gemm_mma_kernel<<<bg, 256>>>(bufA, wt + 3 * 65536, bufB, nullptr, Bv[4], 1);
    gemm_mma_kernel<<<bg, 256>>>(bufB, wt + 4 * 65536, bufA, nullptr, nullptr, 0);

    // ---- logits + softmax
    final_softmax_kernel<<<M / 8, 256>>>(bufA, w_out, b_out, (float*)d_out);
}

// round 8
// speedup vs baseline: 2.1007x; 1.1431x over previous
#include <cuda_runtime.h>
#include <cuda_bf16.h>
#include <math.h>
#include <stdint.h>

// ======================= scratch (no allocation) ============================
__device__ float g_bufA[65536u * 256u];          // final fp32 activations
__device__ __nv_bfloat16 g_s0h[65536u * 256u];   // activation ping (hi)
__device__ __nv_bfloat16 g_s0l[65536u * 256u];   // activation ping (lo)
__device__ __nv_bfloat16 g_s1h[65536u * 256u];   // activation pong (hi)
__device__ __nv_bfloat16 g_s1l[65536u * 256u];   // activation pong (lo)
__device__ __nv_bfloat16 g_wbh[5 * 65536];       // weights^T split hi [z][n][k]
__device__ __nv_bfloat16 g_wbl[5 * 65536];       // weights^T split lo
__device__ float g_Wc  [4 * 65536];
__device__ float g_e2  [4 * 65536];
__device__ float g_e4  [4 * 65536];
__device__ float g_e8  [4 * 65536];
__device__ float g_p1  [4 * 65536];
__device__ float g_p2  [4 * 65536];
__device__ float g_winv[4 * 65536];

// ======================= helpers ===========================================
__device__ __forceinline__ uint32_t smem_u32(const void* p) {
    uint32_t a;
    asm("{ .reg .u64 t; cvta.to.shared.u64 t, %1; cvt.u32.u64 %0, t; }"
        : "=r"(a) : "l"(p));
    return a;
}

#define CPASYNC16(dst, src) \
    asm volatile("cp.async.cg.shared.global [%0], [%1], 16;" \
        :: "r"(dst), "l"(src) : "memory")
#define CPASYNC_COMMIT() asm volatile("cp.async.commit_group;" ::: "memory")
#define CPASYNC_WAIT(n)  asm volatile("cp.async.wait_group %0;" :: "n"(n) : "memory")

__device__ __forceinline__ void ldsm_x4(uint32_t& r0, uint32_t& r1,
                                        uint32_t& r2, uint32_t& r3, uint32_t addr) {
    asm volatile("ldmatrix.sync.aligned.m8n8.x4.shared.b16 {%0,%1,%2,%3}, [%4];"
        : "=r"(r0), "=r"(r1), "=r"(r2), "=r"(r3) : "r"(addr));
}

__device__ __forceinline__ void mma16816(float* c, uint32_t a0, uint32_t a1,
                                         uint32_t a2, uint32_t a3,
                                         uint32_t b0, uint32_t b1) {
    asm volatile("mma.sync.aligned.m16n8k16.row.col.f32.bf16.bf16.f32 "
        "{%0,%1,%2,%3}, {%4,%5,%6,%7}, {%8,%9}, {%0,%1,%2,%3};"
        : "+f"(c[0]), "+f"(c[1]), "+f"(c[2]), "+f"(c[3])
        : "r"(a0), "r"(a1), "r"(a2), "r"(a3), "r"(b0), "r"(b1));
}

// 8 fp32 -> 4 packed bf16x2 hi words + 4 lo words (split precision)
__device__ __forceinline__ void split8(const float* f, uint32_t* hw, uint32_t* lw) {
    #pragma unroll
    for (int j = 0; j < 4; j++) {
        __nv_bfloat16 h0 = __float2bfloat16(f[2 * j]);
        __nv_bfloat16 h1 = __float2bfloat16(f[2 * j + 1]);
        float l0 = f[2 * j] - __bfloat162float(h0);
        float l1 = f[2 * j + 1] - __bfloat162float(h1);
        __nv_bfloat162 hp; hp.x = h0; hp.y = h1;
        __nv_bfloat162 lp; lp.x = __float2bfloat16(l0); lp.y = __float2bfloat16(l1);
        hw[j] = *(uint32_t*)&hp; lw[j] = *(uint32_t*)&lp;
    }
}

__device__ __forceinline__ uint32_t pack_bf2(float a, float b) {
    __nv_bfloat162 p; p.x = __float2bfloat16(a); p.y = __float2bfloat16(b);
    return *(uint32_t*)&p;
}

// ======================= weight prep kernels ================================
__global__ void pack4_kernel(const float* __restrict__ w1, const float* __restrict__ w2,
                             const float* __restrict__ w3, const float* __restrict__ w4,
                             float* __restrict__ dst) {
    int idx = blockIdx.x * blockDim.x + threadIdx.x;
    const float* src = (blockIdx.y == 0) ? w1 : (blockIdx.y == 1) ? w2
                     : (blockIdx.y == 2) ? w3 : w4;
    dst[blockIdx.y * 65536 + idx] = src[idx];
}

// batched small 256x256 GEMM stages for Neumann inversion.
// 64x64 tile per block, 4x4 per thread, float4 smem loads.
__global__ __launch_bounds__(256) void small_stage_kernel(
    int stage, const float* __restrict__ wc, float* __restrict__ e2,
    float* __restrict__ e4, float* __restrict__ e8,
    float* __restrict__ p1, float* __restrict__ p2, float* __restrict__ winv)
{
    int z = blockIdx.z;
    const float *Ap, *Bp; float* Cp;
    float sa = 1.f, ad = 0.f, sb = 1.f, bd = 0.f;
    if (stage == 0) { Ap = wc + z * 65536; Bp = Ap; Cp = e2 + z * 65536; ad = -1.f; bd = -1.f; }
    else if (stage == 1) {
        if (z < 4) { Ap = e2 + z * 65536; Bp = Ap; Cp = e4 + z * 65536; }
        else { int m = z - 4; Ap = wc + m * 65536; sa = -1.f; ad = 2.f;
               Bp = e2 + m * 65536; bd = 1.f; Cp = p1 + m * 65536; }
    } else if (stage == 2) {
        if (z < 4) { Ap = e4 + z * 65536; Bp = Ap; Cp = e8 + z * 65536; }
        else { int m = z - 4; Ap = p1 + m * 65536; Bp = e4 + m * 65536;
               bd = 1.f; Cp = p2 + m * 65536; }
    } else { Ap = p2 + z * 65536; Bp = e8 + z * 65536; bd = 1.f; Cp = winv + z * 65536; }

    __shared__ float As[16][64];    // transposed: [k][m]
    __shared__ float Bs[16][68];    // [k][n], padded (272B rows, 16B aligned)
    int tid = threadIdx.x, tx = tid & 15, ty = tid >> 4;
    int r0 = blockIdx.x * 64, c0 = blockIdx.y * 64;
    float acc[4][4] = {};
    for (int k0 = 0; k0 < 256; k0 += 16) {
        {   // A tile 64x16 -> transposed scalar stores
            int r = tid >> 2, cc = (tid & 3) * 4;
            float4 v = *(const float4*)&Ap[(r0 + r) * 256 + k0 + cc];
            float f[4] = {v.x, v.y, v.z, v.w};
            #pragma unroll
            for (int i = 0; i < 4; i++)
                As[cc + i][r] = f[i] * sa + ((r0 + r) == (k0 + cc + i) ? ad : 0.f);
        }
        {   // B tile 16x64 -> float4 store
            int r = tid >> 4, cc = (tid & 15) * 4;
            float4 v = *(const float4*)&Bp[(k0 + r) * 256 + c0 + cc];
            float f[4] = {v.x, v.y, v.z, v.w};
            #pragma unroll
            for (int i = 0; i < 4; i++)
                f[i] = f[i] * sb + ((k0 + r) == (c0 + cc + i) ? bd : 0.f);
            *(float4*)&Bs[r][cc] = make_float4(f[0], f[1], f[2], f[3]);
        }
        __syncthreads();
        #pragma unroll
        for (int kk = 0; kk < 16; kk++) {
            float4 a4 = *(const float4*)&As[kk][ty * 4];
            float4 b4 = *(const float4*)&Bs[kk][tx * 4];
            float a[4] = {a4.x, a4.y, a4.z, a4.w};
            float b[4] = {b4.x, b4.y, b4.z, b4.w};
            #pragma unroll
            for (int i = 0; i < 4; i++)
                #pragma unroll
                for (int j = 0; j < 4; j++)
                    acc[i][j] += a[i] * b[j];
        }
        __syncthreads();
    }
    #pragma unroll
    for (int i = 0; i < 4; i++) {
        float4 v = make_float4(acc[i][0], acc[i][1], acc[i][2], acc[i][3]);
        *(float4*)&Cp[(size_t)(r0 + ty * 4 + i) * 256 + c0 + tx * 4] = v;
    }
}

// transpose + split w_in, Winv1..4 -> wbh/wbl [z][n][k] = split(W[k][n])
__global__ void transpose5_split_kernel(const float* __restrict__ w_in,
                                        const float* __restrict__ winv,
                                        __nv_bfloat16* __restrict__ wbh,
                                        __nv_bfloat16* __restrict__ wbl) {
    __shared__ float t[32][33];
    int z = blockIdx.z;
    const float* src = (z == 0) ? w_in : winv + (z - 1) * 65536;
    int x = blockIdx.x * 32 + threadIdx.x;
    int y = blockIdx.y * 32 + threadIdx.y;
    t[threadIdx.y][threadIdx.x] = src[y * 256 + x];
    __syncthreads();
    int ox = blockIdx.y * 32 + threadIdx.x;
    int oy = blockIdx.x * 32 + threadIdx.y;
    float v = t[threadIdx.x][threadIdx.y];
    __nv_bfloat16 h = __float2bfloat16(v);
    float l = v - __bfloat162float(h);
    wbh[z * 65536 + oy * 256 + ox] = h;
    wbl[z * 65536 + oy * 256 + ox] = __float2bfloat16(l);
}

// split x fp32 -> xh/xl bf16 (8 elements per thread)
__global__ __launch_bounds__(256) void split_x_kernel(
    const float* __restrict__ x, __nv_bfloat16* __restrict__ xh,
    __nv_bfloat16* __restrict__ xl) {
    size_t i = (size_t)blockIdx.x * 256 + threadIdx.x;
    const float4* src = (const float4*)(x + i * 8);
    float4 v0 = src[0], v1 = src[1];
    float f[8] = {v0.x, v0.y, v0.z, v0.w, v1.x, v1.y, v1.z, v1.w};
    uint32_t hw[4], lw[4];
    split8(f, hw, lw);
    *(uint4*)(xh + i * 8) = make_uint4(hw[0], hw[1], hw[2], hw[3]);
    *(uint4*)(xl + i * 8) = make_uint4(lw[0], lw[1], lw[2], lw[3]);
}

// ======================= big GEMM: bf16-split HMMA, cp.async pipeline =======
// C = A @ W; A given split (Ah,Al) [M,256] bf16; W^T split (Bh,Bl) [256,256].
// D = Ah*Bh + Ah*Bl + Al*Bh (fp32 regs).
// mode1: v = D (+bias1); u = v + tanh(v) + bias2 -> split to Ch/Cl bf16.
// mode0: v = D -> Cf fp32.
// CTA 128x256 (full N), 512 threads (16 warps = 4M x 4N), warp tile 32x64.
// K chunks of 32, 2-stage cp.async ping-pong.
#define PADK 40
#define ST_A   (128 * PADK * 2)            // 10240 B per A tile
#define ST_B   (256 * PADK * 2)            // 20480 B per B tile
#define ST_SZ  (2 * ST_A + 2 * ST_B)       // 61440 B per stage
#define SM_TOT (2 * ST_SZ)                 // 122880 B
#define O_AH 0
#define O_AL ST_A
#define O_BH (2 * ST_A)
#define O_BL (2 * ST_A + ST_B)

__global__ __launch_bounds__(512, 1) void gemm_mma_kernel(
    const __nv_bfloat16* __restrict__ Ah, const __nv_bfloat16* __restrict__ Al,
    const __nv_bfloat16* __restrict__ Bh, const __nv_bfloat16* __restrict__ Bl,
    __nv_bfloat16* __restrict__ Ch, __nv_bfloat16* __restrict__ Cl,
    float* __restrict__ Cf,
    const float* __restrict__ bias1, const float* __restrict__ bias2, int mode)
{
    extern __shared__ char smem[];
    uint32_t sbase = smem_u32(smem);
    int tid = threadIdx.x, wid = tid >> 5, lane = tid & 31;
    int m0 = blockIdx.x * 128;
    int wm = wid & 3, wn = wid >> 2;

    // ---- cp.async fill of one chunk into stage st
    auto fill = [&](int c, int st) {
        uint32_t sg = sbase + st * ST_SZ;
        int kc = c * 32;
        {   // A: 128 rows x 32k, hi+lo: 512 x 16B each
            int m = tid >> 2, ch = tid & 3;
            uint32_t doff = (uint32_t)(m * PADK) * 2 + ch * 16;
            size_t goff = (size_t)(m0 + m) * 256 + kc + ch * 8;
            CPASYNC16(sg + O_AH + doff, Ah + goff);
            CPASYNC16(sg + O_AL + doff, Al + goff);
        }
        #pragma unroll
        for (int it = 0; it < 2; it++) {    // B: 256 rows x 32k, hi+lo
            int g = tid + it * 512;
            int n = g >> 2, ch = g & 3;
            uint32_t doff = (uint32_t)(n * PADK) * 2 + ch * 16;
            size_t goff = (size_t)n * 256 + kc + ch * 8;
            CPASYNC16(sg + O_BH + doff, Bh + goff);
            CPASYNC16(sg + O_BL + doff, Bl + goff);
        }
    };

    float acc[2][4][2][4];
    #pragma unroll
    for (int i = 0; i < 2; i++)
        #pragma unroll
        for (int j = 0; j < 4; j++)
            #pragma unroll
            for (int s = 0; s < 2; s++)
                #pragma unroll
                for (int q = 0; q < 4; q++) acc[i][j][s][q] = 0.f;

    fill(0, 0);
    CPASYNC_COMMIT();

    for (int c = 0; c < 8; c++) {
        if (c < 7) { fill(c + 1, (c + 1) & 1); CPASYNC_COMMIT(); }
        if (c < 7) { CPASYNC_WAIT(1); } else { CPASYNC_WAIT(0); }
        __syncthreads();

        uint32_t sg = sbase + (c & 1) * ST_SZ;
        uint32_t bAh = sg + O_AH, bAl = sg + O_AL;
        uint32_t bBh = sg + O_BH, bBl = sg + O_BL;

        #pragma unroll
        for (int ks = 0; ks < 2; ks++) {
            int koff = ks * 16 + ((lane >> 4) << 3);
            uint32_t ah[2][4], al[2][4];
            #pragma unroll
            for (int mf = 0; mf < 2; mf++) {
                uint32_t row = (uint32_t)(wm * 32 + mf * 16 + (lane & 15));
                uint32_t o = (row * PADK + koff) * 2;
                ldsm_x4(ah[mf][0], ah[mf][1], ah[mf][2], ah[mf][3], bAh + o);
                ldsm_x4(al[mf][0], al[mf][1], al[mf][2], al[mf][3], bAl + o);
            }
            #pragma unroll
            for (int nfp = 0; nfp < 4; nfp++) {
                uint32_t row = (uint32_t)(wn * 64 + nfp * 16 + (lane & 15));
                uint32_t o = (row * PADK + koff) * 2;
                uint32_t bh0, bh1, bh2, bh3, bl0, bl1, bl2, bl3;
                ldsm_x4(bh0, bh1, bh2, bh3, bBh + o);
                ldsm_x4(bl0, bl1, bl2, bl3, bBl + o);
                #pragma unroll
                for (int mf = 0; mf < 2; mf++) {
                    mma16816(acc[mf][nfp][0], ah[mf][0], ah[mf][1], ah[mf][2], ah[mf][3], bh0, bh2);
                    mma16816(acc[mf][nfp][0], ah[mf][0], ah[mf][1], ah[mf][2], ah[mf][3], bl0, bl2);
                    mma16816(acc[mf][nfp][0], al[mf][0], al[mf][1], al[mf][2], al[mf][3], bh0, bh2);
                    mma16816(acc[mf][nfp][1], ah[mf][0], ah[mf][1], ah[mf][2], ah[mf][3], bh1, bh3);
                    mma16816(acc[mf][nfp][1], ah[mf][0], ah[mf][1], ah[mf][2], ah[mf][3], bl1, bl3);
                    mma16816(acc[mf][nfp][1], al[mf][0], al[mf][1], al[mf][2], al[mf][3], bh1, bh3);
                }
            }
        }
        __syncthreads();
    }

    // ---- epilogue
    #pragma unroll
    for (int mf = 0; mf < 2; mf++) {
        int row = m0 + wm * 32 + mf * 16 + (lane >> 2);
        #pragma unroll
        for (int nfp = 0; nfp < 4; nfp++) {
            #pragma unroll
            for (int s = 0; s < 2; s++) {
                int col = wn * 64 + nfp * 16 + s * 8 + (lane & 3) * 2;
                float b1a = bias1 ? __ldg(bias1 + col)     : 0.f;
                float b1b = bias1 ? __ldg(bias1 + col + 1) : 0.f;
                float v0 = acc[mf][nfp][s][0] + b1a;
                float v1 = acc[mf][nfp][s][1] + b1b;
                float v2 = acc[mf][nfp][s][2] + b1a;
                float v3 = acc[mf][nfp][s][3] + b1b;
                if (mode) {
                    float b2a = __ldg(bias2 + col), b2b = __ldg(bias2 + col + 1);
                    v0 = v0 + tanhf(v0) + b2a;
                    v1 = v1 + tanhf(v1) + b2b;
                    v2 = v2 + tanhf(v2) + b2a;
                    v3 = v3 + tanhf(v3) + b2b;
                    // split to hi/lo bf16
                    size_t o0 = (size_t)row * 256 + col;
                    size_t o1 = (size_t)(row + 8) * 256 + col;
                    uint32_t h01 = pack_bf2(v0, v1);
                    float r0 = v0 - __bfloat162float(__float2bfloat16(v0));
                    float r1 = v1 - __bfloat162float(__float2bfloat16(v1));
                    *(uint32_t*)(Ch + o0) = h01;
                    *(uint32_t*)(Cl + o0) = pack_bf2(r0, r1);
                    uint32_t h23 = pack_bf2(v2, v3);
                    float r2 = v2 - __bfloat162float(__float2bfloat16(v2));
                    float r3 = v3 - __bfloat162float(__float2bfloat16(v3));
                    *(uint32_t*)(Ch + o1) = h23;
                    *(uint32_t*)(Cl + o1) = pack_bf2(r2, r3);
                } else {
                    *(float2*)(Cf + (size_t)row * 256 + col)       = make_float2(v0, v1);
                    *(float2*)(Cf + (size_t)(row + 8) * 256 + col) = make_float2(v2, v3);
                }
            }
        }
    }
}

// ======================= logits + softmax ===================================
__global__ __launch_bounds__(256) void final_softmax_kernel(
    const float* __restrict__ Z, const float* __restrict__ w_out,
    const float* __restrict__ b_out, float* __restrict__ out)
{
    __shared__ float ws[2560];
    __shared__ float bs[10];
    int tid = threadIdx.x;
    for (int i = tid; i < 2560; i += 256) ws[i] = w_out[i];
    if (tid < 10) bs[tid] = b_out[tid];
    __syncthreads();

    int warp = tid >> 5, lane = tid & 31;
    int row = blockIdx.x * 8 + warp;
    float acc[10] = {};
    const float4* zr = reinterpret_cast<const float4*>(Z + (size_t)row * 256);
    for (int i = lane; i < 64; i += 32) {
        float4 v = zr[i];
        int k = i * 4;
        #pragma unroll
        for (int j = 0; j < 10; j++)
            acc[j] += v.x * ws[(k + 0) * 10 + j] + v.y * ws[(k + 1) * 10 + j]
                    + v.z * ws[(k + 2) * 10 + j] + v.w * ws[(k + 3) * 10 + j];
    }
    #pragma unroll
    for (int j = 0; j < 10; j++) {
        float v = acc[j];
        #pragma unroll
        for (int o = 16; o; o >>= 1) v += __shfl_xor_sync(0xFFFFFFFFu, v, o);
        acc[j] = v;
    }
    if (lane == 0) {
        float m = -1e30f;
        #pragma unroll
        for (int j = 0; j < 10; j++) { acc[j] += bs[j]; m = fmaxf(m, acc[j]); }
        float s = 0.f;
        #pragma unroll
        for (int j = 0; j < 10; j++) { acc[j] = expf(acc[j] - m); s += acc[j]; }
        float inv = 1.0f / s;
        #pragma unroll
        for (int j = 0; j < 10; j++) out[(size_t)row * 10 + j] = acc[j] * inv;
    }
}

// ======================= launch =============================================
extern "C" void kernel_launch(void* const* d_in, const int* in_sizes, int n_in,
                              void* d_out, int out_size) {
    const float* x = nullptr;
    const float* Wm[5] = {};  int nW = 0;
    const float* Bv[5] = {};  int nB = 0;
    const float* w_out = nullptr;
    const float* b_out = nullptr;
    for (int i = 0; i < n_in; i++) {
        const float* p = (const float*)d_in[i];
        int sz = in_sizes[i];
        if (sz == 65536 * 256)      x = p;
        else if (sz == 65536)       { if (nW < 5) Wm[nW++] = p; }
        else if (sz == 256)         { if (nB < 5) Bv[nB++] = p; }
        else if (sz == 2560)        w_out = p;
        else if (sz == 10)          b_out = p;
    }
    const float* w_in = Wm[0];
    const float* b_in = Bv[0];
    int M = 65536;

    float *bufA, *wc, *e2, *e4, *e8, *p1, *p2, *winv;
    __nv_bfloat16 *s0h, *s0l, *s1h, *s1l, *wbh, *wbl;
    cudaGetSymbolAddress((void**)&bufA, g_bufA);
    cudaGetSymbolAddress((void**)&wc,   g_Wc);
    cudaGetSymbolAddress((void**)&e2,   g_e2);
    cudaGetSymbolAddress((void**)&e4,   g_e4);
    cudaGetSymbolAddress((void**)&e8,   g_e8);
    cudaGetSymbolAddress((void**)&p1,   g_p1);
    cudaGetSymbolAddress((void**)&p2,   g_p2);
    cudaGetSymbolAddress((void**)&winv, g_winv);
    cudaGetSymbolAddress((void**)&s0h,  g_s0h);
    cudaGetSymbolAddress((void**)&s0l,  g_s0l);
    cudaGetSymbolAddress((void**)&s1h,  g_s1h);
    cudaGetSymbolAddress((void**)&s1l,  g_s1l);
    cudaGetSymbolAddress((void**)&wbh,  g_wbh);
    cudaGetSymbolAddress((void**)&wbl,  g_wbl);

    cudaFuncSetAttribute(gemm_mma_kernel,
                         cudaFuncAttributeMaxDynamicSharedMemorySize, SM_TOT);

    // ---- Neumann inverse of W1..W4: Winv = (I-E)(I+E^2)(I+E^4)(I+E^8), E=W-I
    pack4_kernel<<<dim3(256, 4), 256>>>(Wm[1], Wm[2], Wm[3], Wm[4], wc);
    small_stage_kernel<<<dim3(4, 4, 4), 256>>>(0, wc, e2, e4, e8, p1, p2, winv);
    small_stage_kernel<<<dim3(4, 4, 8), 256>>>(1, wc, e2, e4, e8, p1, p2, winv);
    small_stage_kernel<<<dim3(4, 4, 8), 256>>>(2, wc, e2, e4, e8, p1, p2, winv);
    small_stage_kernel<<<dim3(4, 4, 4), 256>>>(3, wc, e2, e4, e8, p1, p2, winv);

    // ---- transpose + split the 5 forward weights; split x
    transpose5_split_kernel<<<dim3(8, 8, 5), dim3(32, 32)>>>(w_in, winv, wbh, wbl);
    split_x_kernel<<<M * 256 / (256 * 8), 256>>>(x, s0h, s0l);

    // ---- forward chain: 5 pipelined HMMA GEMMs
    dim3 bg(M / 128);
    gemm_mma_kernel<<<bg, 512, SM_TOT>>>(s0h, s0l, wbh + 0 * 65536, wbl + 0 * 65536,
                                         s1h, s1l, nullptr, b_in,   Bv[1], 1);
    gemm_mma_kernel<<<bg, 512, SM_TOT>>>(s1h, s1l, wbh + 1 * 65536, wbl + 1 * 65536,
                                         s0h, s0l, nullptr, nullptr, Bv[2], 1);
    gemm_mma_kernel<<<bg, 512, SM_TOT>>>(s0h, s0l, wbh + 2 * 65536, wbl + 2 * 65536,
                                         s1h, s1l, nullptr, nullptr, Bv[3], 1);
    gemm_mma_kernel<<<bg, 512, SM_TOT>>>(s1h, s1l, wbh + 3 * 65536, wbl + 3 * 65536,
                                         s0h, s0l, nullptr, nullptr, Bv[4], 1);
    gemm_mma_kernel<<<bg, 512, SM_TOT>>>(s0h, s0l, wbh + 4 * 65536, wbl + 4 * 65536,
                                         nullptr, nullptr, bufA, nullptr, nullptr, 0);

    // ---- logits + softmax
    final_softmax_kernel<<<M / 8, 256>>>(bufA, w_out, b_out, (float*)d_out);
}

// round 10
// speedup vs baseline: 2.4564x; 1.1693x over previous
#include <cuda_runtime.h>
#include <cuda_bf16.h>
#include <math.h>
#include <stdint.h>

// ======================= scratch (no allocation) ============================
__device__ float g_bufA[65536u * 256u];          // final fp32 activations
__device__ __nv_bfloat16 g_s0h[65536u * 256u];   // activation ping (hi)
__device__ __nv_bfloat16 g_s0l[65536u * 256u];   // activation ping (lo)
__device__ __nv_bfloat16 g_s1h[65536u * 256u];   // activation pong (hi)
__device__ __nv_bfloat16 g_s1l[65536u * 256u];   // activation pong (lo)
__device__ __nv_bfloat16 g_wbh[5 * 65536];       // weights^T split hi [z][n][k]
__device__ __nv_bfloat16 g_wbl[5 * 65536];       // weights^T split lo
__device__ float g_e2[4 * 65536];
__device__ float g_e4[4 * 65536];
__device__ float g_p1[4 * 65536];

// ======================= helpers ===========================================
__device__ __forceinline__ uint32_t smem_u32(const void* p) {
    uint32_t a;
    asm("{ .reg .u64 t; cvta.to.shared.u64 t, %1; cvt.u32.u64 %0, t; }"
        : "=r"(a) : "l"(p));
    return a;
}

#define CPASYNC16(dst, src) \
    asm volatile("cp.async.cg.shared.global [%0], [%1], 16;" \
        :: "r"(dst), "l"(src) : "memory")
#define CPASYNC_COMMIT() asm volatile("cp.async.commit_group;" ::: "memory")
#define CPASYNC_WAIT(n)  asm volatile("cp.async.wait_group %0;" :: "n"(n) : "memory")

__device__ __forceinline__ void ldsm_x4(uint32_t& r0, uint32_t& r1,
                                        uint32_t& r2, uint32_t& r3, uint32_t addr) {
    asm volatile("ldmatrix.sync.aligned.m8n8.x4.shared.b16 {%0,%1,%2,%3}, [%4];"
        : "=r"(r0), "=r"(r1), "=r"(r2), "=r"(r3) : "r"(addr));
}

__device__ __forceinline__ void mma16816(float* c, uint32_t a0, uint32_t a1,
                                         uint32_t a2, uint32_t a3,
                                         uint32_t b0, uint32_t b1) {
    asm volatile("mma.sync.aligned.m16n8k16.row.col.f32.bf16.bf16.f32 "
        "{%0,%1,%2,%3}, {%4,%5,%6,%7}, {%8,%9}, {%0,%1,%2,%3};"
        : "+f"(c[0]), "+f"(c[1]), "+f"(c[2]), "+f"(c[3])
        : "r"(a0), "r"(a1), "r"(a2), "r"(a3), "r"(b0), "r"(b1));
}

__device__ __forceinline__ void split8(const float* f, uint32_t* hw, uint32_t* lw) {
    #pragma unroll
    for (int j = 0; j < 4; j++) {
        __nv_bfloat16 h0 = __float2bfloat16(f[2 * j]);
        __nv_bfloat16 h1 = __float2bfloat16(f[2 * j + 1]);
        float l0 = f[2 * j] - __bfloat162float(h0);
        float l1 = f[2 * j + 1] - __bfloat162float(h1);
        __nv_bfloat162 hp; hp.x = h0; hp.y = h1;
        __nv_bfloat162 lp; lp.x = __float2bfloat16(l0); lp.y = __float2bfloat16(l1);
        hw[j] = *(uint32_t*)&hp; lw[j] = *(uint32_t*)&lp;
    }
}

__device__ __forceinline__ uint32_t pack_bf2(float a, float b) {
    __nv_bfloat162 p; p.x = __float2bfloat16(a); p.y = __float2bfloat16(b);
    return *(uint32_t*)&p;
}

// ======================= weight prep ========================================
// split x fp32 -> xh/xl bf16 (8 elements per thread)
__global__ __launch_bounds__(256) void split_x_kernel(
    const float* __restrict__ x, __nv_bfloat16* __restrict__ xh,
    __nv_bfloat16* __restrict__ xl) {
    size_t i = (size_t)blockIdx.x * 256 + threadIdx.x;
    const float4* src = (const float4*)(x + i * 8);
    float4 v0 = src[0], v1 = src[1];
    float f[8] = {v0.x, v0.y, v0.z, v0.w, v1.x, v1.y, v1.z, v1.w};
    uint32_t hw[4], lw[4];
    split8(f, hw, lw);
    *(uint4*)(xh + i * 8) = make_uint4(hw[0], hw[1], hw[2], hw[3]);
    *(uint4*)(xl + i * 8) = make_uint4(lw[0], lw[1], lw[2], lw[3]);
}

// transpose + split w_in -> slice 0 of wbh/wbl
__global__ void win_transpose_split_kernel(const float* __restrict__ w_in,
                                           __nv_bfloat16* __restrict__ wbh,
                                           __nv_bfloat16* __restrict__ wbl) {
    __shared__ float t[32][33];
    int x = blockIdx.x * 32 + threadIdx.x;
    int y = blockIdx.y * 32 + threadIdx.y;
    t[threadIdx.y][threadIdx.x] = w_in[y * 256 + x];
    __syncthreads();
    int ox = blockIdx.y * 32 + threadIdx.x;
    int oy = blockIdx.x * 32 + threadIdx.y;
    float v = t[threadIdx.x][threadIdx.y];
    __nv_bfloat16 h = __float2bfloat16(v);
    wbh[oy * 256 + ox] = h;
    wbl[oy * 256 + ox] = __float2bfloat16(v - __bfloat162float(h));
}

// Neumann inversion, truncated at E^7: Winv = (I-E)(I+E^2)(I+E^4), E = W-I.
// stage 0 (z=0..3):  E2 = (W-I)(W-I)
// stage 1 (z=0..7):  z<4: E4 = E2*E2 ;  z>=4: P1 = (I-E)(I+E2) = (2I-W)(I+E2)
// stage 2 (z=0..3):  Winv = P1*(I+E4) -> written TRANSPOSED+SPLIT to wb[z+1]
__global__ __launch_bounds__(256) void small_stage_kernel(
    int stage,
    const float* __restrict__ w1, const float* __restrict__ w2,
    const float* __restrict__ w3, const float* __restrict__ w4,
    float* __restrict__ e2, float* __restrict__ e4, float* __restrict__ p1,
    __nv_bfloat16* __restrict__ wbh, __nv_bfloat16* __restrict__ wbl)
{
    int z = blockIdx.z;
    int m = z & 3;
    const float* W = (m == 0) ? w1 : (m == 1) ? w2 : (m == 2) ? w3 : w4;
    const float *Ap, *Bp; float* Cp = nullptr;
    float sa = 1.f, ad = 0.f, sb = 1.f, bd = 0.f;
    int tsplit = 0;
    if (stage == 0) { Ap = W; ad = -1.f; Bp = W; bd = -1.f; Cp = e2 + m * 65536; }
    else if (stage == 1) {
        if (z < 4) { Ap = e2 + m * 65536; Bp = Ap; Cp = e4 + m * 65536; }
        else { Ap = W; sa = -1.f; ad = 2.f; Bp = e2 + m * 65536; bd = 1.f; Cp = p1 + m * 65536; }
    } else { Ap = p1 + m * 65536; Bp = e4 + m * 65536; bd = 1.f; tsplit = 1; }

    __shared__ float As[16][64];
    __shared__ float Bs[16][68];
    int tid = threadIdx.x, tx = tid & 15, ty = tid >> 4;
    int r0 = blockIdx.x * 64, c0 = blockIdx.y * 64;
    float acc[4][4] = {};
    for (int k0 = 0; k0 < 256; k0 += 16) {
        {
            int r = tid >> 2, cc = (tid & 3) * 4;
            float4 v = *(const float4*)&Ap[(r0 + r) * 256 + k0 + cc];
            float f[4] = {v.x, v.y, v.z, v.w};
            #pragma unroll
            for (int i = 0; i < 4; i++)
                As[cc + i][r] = f[i] * sa + ((r0 + r) == (k0 + cc + i) ? ad : 0.f);
        }
        {
            int r = tid >> 4, cc = (tid & 15) * 4;
            float4 v = *(const float4*)&Bp[(k0 + r) * 256 + c0 + cc];
            float f[4] = {v.x, v.y, v.z, v.w};
            #pragma unroll
            for (int i = 0; i < 4; i++)
                f[i] = f[i] * sb + ((k0 + r) == (c0 + cc + i) ? bd : 0.f);
            *(float4*)&Bs[r][cc] = make_float4(f[0], f[1], f[2], f[3]);
        }
        __syncthreads();
        #pragma unroll
        for (int kk = 0; kk < 16; kk++) {
            float4 a4 = *(const float4*)&As[kk][ty * 4];
            float4 b4 = *(const float4*)&Bs[kk][tx * 4];
            float a[4] = {a4.x, a4.y, a4.z, a4.w};
            float b[4] = {b4.x, b4.y, b4.z, b4.w};
            #pragma unroll
            for (int i = 0; i < 4; i++)
                #pragma unroll
                for (int j = 0; j < 4; j++)
                    acc[i][j] += a[i] * b[j];
        }
        __syncthreads();
    }
    if (!tsplit) {
        #pragma unroll
        for (int i = 0; i < 4; i++)
            *(float4*)&Cp[(size_t)(r0 + ty * 4 + i) * 256 + c0 + tx * 4] =
                make_float4(acc[i][0], acc[i][1], acc[i][2], acc[i][3]);
    } else {
        // Winv[r][c] -> wb[(m+1)][c][r] split (transposed scatter)
        __nv_bfloat16* dh = wbh + (m + 1) * 65536;
        __nv_bfloat16* dl = wbl + (m + 1) * 65536;
        #pragma unroll
        for (int i = 0; i < 4; i++)
            #pragma unroll
            for (int j = 0; j < 4; j++) {
                int r = r0 + ty * 4 + i, c = c0 + tx * 4 + j;
                float v = acc[i][j];
                __nv_bfloat16 h = __float2bfloat16(v);
                dh[c * 256 + r] = h;
                dl[c * 256 + r] = __float2bfloat16(v - __bfloat162float(h));
            }
    }
}

// ======================= big GEMM: bf16-split HMMA, cp.async pipeline =======
// CTA tile 128x128, 256 threads (8 warps = 4M x 2N), warp tile 32x64.
// K chunks of 32, 2-stage ping-pong, 2 CTAs/SM (80KB smem each).
#define PADK 40
#define ST_A   (128 * PADK * 2)            // 10240 B per tile
#define ST_SZ  (4 * ST_A)                  // 40960 B per stage (Ah,Al,Bh,Bl)
#define SM_TOT (2 * ST_SZ)                 // 81920 B
#define O_AH 0
#define O_AL ST_A
#define O_BH (2 * ST_A)
#define O_BL (3 * ST_A)

__global__ __launch_bounds__(256, 2) void gemm_mma_kernel(
    const __nv_bfloat16* __restrict__ Ah, const __nv_bfloat16* __restrict__ Al,
    const __nv_bfloat16* __restrict__ Bh, const __nv_bfloat16* __restrict__ Bl,
    __nv_bfloat16* __restrict__ Ch, __nv_bfloat16* __restrict__ Cl,
    float* __restrict__ Cf,
    const float* __restrict__ bias1, const float* __restrict__ bias2, int mode)
{
    extern __shared__ char smem[];
    uint32_t sbase = smem_u32(smem);
    int tid = threadIdx.x, wid = tid >> 5, lane = tid & 31;
    int m0 = blockIdx.x * 128, bn = blockIdx.y * 128;
    int wm = wid & 3, wn = wid >> 2;          // 4 M-warps x 2 N-warps

    auto fill = [&](int c, int st) {
        uint32_t sg = sbase + st * ST_SZ;
        int kc = c * 32;
        #pragma unroll
        for (int it = 0; it < 2; it++) {      // A: 128 rows x 32k (hi+lo)
            int g = tid + it * 256;           // 0..511
            int m = g >> 2, ch = g & 3;
            uint32_t doff = (uint32_t)(m * PADK) * 2 + ch * 16;
            size_t goff = (size_t)(m0 + m) * 256 + kc + ch * 8;
            CPASYNC16(sg + O_AH + doff, Ah + goff);
            CPASYNC16(sg + O_AL + doff, Al + goff);
        }
        #pragma unroll
        for (int it = 0; it < 2; it++) {      // B: 128 n-rows x 32k (hi+lo)
            int g = tid + it * 256;
            int n = g >> 2, ch = g & 3;
            uint32_t doff = (uint32_t)(n * PADK) * 2 + ch * 16;
            size_t goff = (size_t)(bn + n) * 256 + kc + ch * 8;
            CPASYNC16(sg + O_BH + doff, Bh + goff);
            CPASYNC16(sg + O_BL + doff, Bl + goff);
        }
    };

    float acc[2][4][2][4];
    #pragma unroll
    for (int i = 0; i < 2; i++)
        #pragma unroll
        for (int j = 0; j < 4; j++)
            #pragma unroll
            for (int s = 0; s < 2; s++)
                #pragma unroll
                for (int q = 0; q < 4; q++) acc[i][j][s][q] = 0.f;

    fill(0, 0);
    CPASYNC_COMMIT();

    for (int c = 0; c < 8; c++) {
        if (c < 7) { fill(c + 1, (c + 1) & 1); CPASYNC_COMMIT(); }
        if (c < 7) { CPASYNC_WAIT(1); } else { CPASYNC_WAIT(0); }
        __syncthreads();

        uint32_t sg = sbase + (c & 1) * ST_SZ;
        uint32_t bAh = sg + O_AH, bAl = sg + O_AL;
        uint32_t bBh = sg + O_BH, bBl = sg + O_BL;

        #pragma unroll
        for (int ks = 0; ks < 2; ks++) {
            int koff = ks * 16 + ((lane >> 4) << 3);
            uint32_t ah[2][4], al[2][4];
            #pragma unroll
            for (int mf = 0; mf < 2; mf++) {
                uint32_t row = (uint32_t)(wm * 32 + mf * 16 + (lane & 15));
                uint32_t o = (row * PADK + koff) * 2;
                ldsm_x4(ah[mf][0], ah[mf][1], ah[mf][2], ah[mf][3], bAh + o);
                ldsm_x4(al[mf][0], al[mf][1], al[mf][2], al[mf][3], bAl + o);
            }
            #pragma unroll
            for (int nfp = 0; nfp < 4; nfp++) {
                uint32_t row = (uint32_t)(wn * 64 + nfp * 16 + (lane & 15));
                uint32_t o = (row * PADK + koff) * 2;
                uint32_t bh0, bh1, bh2, bh3, bl0, bl1, bl2, bl3;
                ldsm_x4(bh0, bh1, bh2, bh3, bBh + o);
                ldsm_x4(bl0, bl1, bl2, bl3, bBl + o);
                #pragma unroll
                for (int mf = 0; mf < 2; mf++) {
                    mma16816(acc[mf][nfp][0], ah[mf][0], ah[mf][1], ah[mf][2], ah[mf][3], bh0, bh2);
                    mma16816(acc[mf][nfp][0], ah[mf][0], ah[mf][1], ah[mf][2], ah[mf][3], bl0, bl2);
                    mma16816(acc[mf][nfp][0], al[mf][0], al[mf][1], al[mf][2], al[mf][3], bh0, bh2);
                    mma16816(acc[mf][nfp][1], ah[mf][0], ah[mf][1], ah[mf][2], ah[mf][3], bh1, bh3);
                    mma16816(acc[mf][nfp][1], ah[mf][0], ah[mf][1], ah[mf][2], ah[mf][3], bl1, bl3);
                    mma16816(acc[mf][nfp][1], al[mf][0], al[mf][1], al[mf][2], al[mf][3], bh1, bh3);
                }
            }
        }
        __syncthreads();
    }

    // ---- epilogue
    #pragma unroll
    for (int mf = 0; mf < 2; mf++) {
        int row = m0 + wm * 32 + mf * 16 + (lane >> 2);
        #pragma unroll
        for (int nfp = 0; nfp < 4; nfp++) {
            #pragma unroll
            for (int s = 0; s < 2; s++) {
                int col = bn + wn * 64 + nfp * 16 + s * 8 + (lane & 3) * 2;
                float b1a = bias1 ? __ldg(bias1 + col)     : 0.f;
                float b1b = bias1 ? __ldg(bias1 + col + 1) : 0.f;
                float v0 = acc[mf][nfp][s][0] + b1a;
                float v1 = acc[mf][nfp][s][1] + b1b;
                float v2 = acc[mf][nfp][s][2] + b1a;
                float v3 = acc[mf][nfp][s][3] + b1b;
                if (mode) {
                    float b2a = __ldg(bias2 + col), b2b = __ldg(bias2 + col + 1);
                    v0 = v0 + tanhf(v0) + b2a;
                    v1 = v1 + tanhf(v1) + b2b;
                    v2 = v2 + tanhf(v2) + b2a;
                    v3 = v3 + tanhf(v3) + b2b;
                    size_t o0 = (size_t)row * 256 + col;
                    size_t o1 = (size_t)(row + 8) * 256 + col;
                    uint32_t h01 = pack_bf2(v0, v1);
                    float r0 = v0 - __bfloat162float(__float2bfloat16(v0));
                    float r1 = v1 - __bfloat162float(__float2bfloat16(v1));
                    *(uint32_t*)(Ch + o0) = h01;
                    *(uint32_t*)(Cl + o0) = pack_bf2(r0, r1);
                    uint32_t h23 = pack_bf2(v2, v3);
                    float r2 = v2 - __bfloat162float(__float2bfloat16(v2));
                    float r3 = v3 - __bfloat162float(__float2bfloat16(v3));
                    *(uint32_t*)(Ch + o1) = h23;
                    *(uint32_t*)(Cl + o1) = pack_bf2(r2, r3);
                } else {
                    *(float2*)(Cf + (size_t)row * 256 + col)       = make_float2(v0, v1);
                    *(float2*)(Cf + (size_t)(row + 8) * 256 + col) = make_float2(v2, v3);
                }
            }
        }
    }
}

// ======================= logits + softmax ===================================
__global__ __launch_bounds__(256) void final_softmax_kernel(
    const float* __restrict__ Z, const float* __restrict__ w_out,
    const float* __restrict__ b_out, float* __restrict__ out)
{
    __shared__ float ws[2560];
    __shared__ float bs[10];
    int tid = threadIdx.x;
    for (int i = tid; i < 2560; i += 256) ws[i] = w_out[i];
    if (tid < 10) bs[tid] = b_out[tid];
    __syncthreads();

    int warp = tid >> 5, lane = tid & 31;
    int row = blockIdx.x * 8 + warp;
    float acc[10] = {};
    const float4* zr = reinterpret_cast<const float4*>(Z + (size_t)row * 256);
    for (int i = lane; i < 64; i += 32) {
        float4 v = zr[i];
        int k = i * 4;
        #pragma unroll
        for (int j = 0; j < 10; j++)
            acc[j] += v.x * ws[(k + 0) * 10 + j] + v.y * ws[(k + 1) * 10 + j]
                    + v.z * ws[(k + 2) * 10 + j] + v.w * ws[(k + 3) * 10 + j];
    }
    #pragma unroll
    for (int j = 0; j < 10; j++) {
        float v = acc[j];
        #pragma unroll
        for (int o = 16; o; o >>= 1) v += __shfl_xor_sync(0xFFFFFFFFu, v, o);
        acc[j] = v;
    }
    if (lane == 0) {
        float m = -1e30f;
        #pragma unroll
        for (int j = 0; j < 10; j++) { acc[j] += bs[j]; m = fmaxf(m, acc[j]); }
        float s = 0.f;
        #pragma unroll
        for (int j = 0; j < 10; j++) { acc[j] = expf(acc[j] - m); s += acc[j]; }
        float inv = 1.0f / s;
        #pragma unroll
        for (int j = 0; j < 10; j++) out[(size_t)row * 10 + j] = acc[j] * inv;
    }
}

// ======================= launch =============================================
extern "C" void kernel_launch(void* const* d_in, const int* in_sizes, int n_in,
                              void* d_out, int out_size) {
    const float* x = nullptr;
    const float* Wm[5] = {};  int nW = 0;
    const float* Bv[5] = {};  int nB = 0;
    const float* w_out = nullptr;
    const float* b_out = nullptr;
    for (int i = 0; i < n_in; i++) {
        const float* p = (const float*)d_in[i];
        int sz = in_sizes[i];
        if (sz == 65536 * 256)      x = p;
        else if (sz == 65536)       { if (nW < 5) Wm[nW++] = p; }
        else if (sz == 256)         { if (nB < 5) Bv[nB++] = p; }
        else if (sz == 2560)        w_out = p;
        else if (sz == 10)          b_out = p;
    }
    const float* w_in = Wm[0];
    const float* b_in = Bv[0];
    int M = 65536;

    float *bufA, *e2, *e4, *p1;
    __nv_bfloat16 *s0h, *s0l, *s1h, *s1l, *wbh, *wbl;
    cudaGetSymbolAddress((void**)&bufA, g_bufA);
    cudaGetSymbolAddress((void**)&e2,   g_e2);
    cudaGetSymbolAddress((void**)&e4,   g_e4);
    cudaGetSymbolAddress((void**)&p1,   g_p1);
    cudaGetSymbolAddress((void**)&s0h,  g_s0h);
    cudaGetSymbolAddress((void**)&s0l,  g_s0l);
    cudaGetSymbolAddress((void**)&s1h,  g_s1h);
    cudaGetSymbolAddress((void**)&s1l,  g_s1l);
    cudaGetSymbolAddress((void**)&wbh,  g_wbh);
    cudaGetSymbolAddress((void**)&wbl,  g_wbl);

    cudaFuncSetAttribute(gemm_mma_kernel,
                         cudaFuncAttributeMaxDynamicSharedMemorySize, SM_TOT);

    // ---- prep: split x; transpose+split w_in; 3-stage Neumann inverse
    split_x_kernel<<<M * 256 / (256 * 8), 256>>>(x, s0h, s0l);
    win_transpose_split_kernel<<<dim3(8, 8), dim3(32, 32)>>>(w_in, wbh, wbl);
    small_stage_kernel<<<dim3(4, 4, 4), 256>>>(0, Wm[1], Wm[2], Wm[3], Wm[4],
                                               e2, e4, p1, wbh, wbl);
    small_stage_kernel<<<dim3(4, 4, 8), 256>>>(1, Wm[1], Wm[2], Wm[3], Wm[4],
                                               e2, e4, p1, wbh, wbl);
    small_stage_kernel<<<dim3(4, 4, 4), 256>>>(2, Wm[1], Wm[2], Wm[3], Wm[4],
                                               e2, e4, p1, wbh, wbl);

    // ---- forward chain: 5 pipelined HMMA GEMMs (grid M/128 x 2 N-blocks)
    dim3 bg(M / 128, 2);
    gemm_mma_kernel<<<bg, 256, SM_TOT>>>(s0h, s0l, wbh + 0 * 65536, wbl + 0 * 65536,
                                         s1h, s1l, nullptr, b_in,   Bv[1], 1);
    gemm_mma_kernel<<<bg, 256, SM_TOT>>>(s1h, s1l, wbh + 1 * 65536, wbl + 1 * 65536,
                                         s0h, s0l, nullptr, nullptr, Bv[2], 1);
    gemm_mma_kernel<<<bg, 256, SM_TOT>>>(s0h, s0l, wbh + 2 * 65536, wbl + 2 * 65536,
                                         s1h, s1l, nullptr, nullptr, Bv[3], 1);
    gemm_mma_kernel<<<bg, 256, SM_TOT>>>(s1h, s1l, wbh + 3 * 65536, wbl + 3 * 65536,
                                         s0h, s0l, nullptr, nullptr, Bv[4], 1);
    gemm_mma_kernel<<<bg, 256, SM_TOT>>>(s0h, s0l, wbh + 4 * 65536, wbl + 4 * 65536,
                                         nullptr, nullptr, bufA, nullptr, nullptr, 0);

    // ---- logits + softmax
    final_softmax_kernel<<<M / 8, 256>>>(bufA, w_out, b_out, (float*)d_out);
}